// round 15
// baseline (speedup 1.0000x reference)
#include <cuda_runtime.h>

// ---------------------------------------------------------------------------
// One-pole IIR scan:  out_t = b0*x_t + s_{t-1};  s_t = b1*x_t + a*out_t
// State-only form:    s_t = k*x_t + a*s_{t-1},   k = b1 + a*b0  (a = clamp(a1))
//
// Single fused pass, chunked over time; each chunk warms its state up from
// zero W steps early with |a|^W < 2^-18 (rel-err budget is 1e-3; leaked
// contribution ~4e-6 -> ~100x margin). W clamps to the chunk start, so the
// result is exact for any |a| (chunk 0 always uses the true initial state).
//
// Execution structure (validated R7/R10): 592 blocks = exactly 4/SM on
// 148 SMs, 256 threads/block, loads explicitly batched 8-at-a-time into a
// register array (64 B/thread in LSU flight). v[] is reused as the output
// buffer to stay under the 64-reg cap; main-loop loads use __ldcs
// (read-once) and stores __stcs so streams don't thrash L2.
// ---------------------------------------------------------------------------

#define NUM_SMS 148

__device__ __forceinline__ float clamp_a(float a) {
    return fminf(fmaxf(a, -1.0f), 1.0f);
}

__device__ __forceinline__ int warmup_len(float a, int t0) {
    float la = fabsf(a);
    int W;
    if (la >= 0.999999f) {
        W = t0;                          // exact: run from t=0
    } else if (la <= 1e-30f) {
        W = 2;
    } else {
        float w = ceilf(18.0f / (-__log2f(la)));
        W = (int)w + 1;
        if (W < 2) W = 2;
    }
    if (W > t0) W = t0;
    return W;
}

__global__ void __launch_bounds__(256, 4)
k_fused(const float* __restrict__ x,
        const float* __restrict__ statep,
        const float* __restrict__ b0p,
        const float* __restrict__ b1p,
        const float* __restrict__ a1p,
        float* __restrict__ out,
        float* __restrict__ finalDst,   // may be null
        int T, int B, int L) {
    int c = blockIdx.x * blockDim.x + threadIdx.x;
    if (c >= B) return;
    int chunk = blockIdx.y;

    float a  = clamp_a(a1p[0]);
    float b0 = b0p[0];
    float k  = fmaf(a, b0, b1p[0]);      // k = b1 + a*b0

    int t0 = chunk * L;
    if (t0 >= T) return;
    int tend = t0 + L; if (tend > T) tend = T;

    int W = warmup_len(a, t0);
    int start = t0 - W;

    float s = (start == 0) ? statep[c] : 0.0f;

    // --- warmup: state-only, batch-8 loads (normal cache policy) ---
    {
        const float* p = x + (long)start * B + c;
        int nw = t0 - start;
        int nw8 = nw & ~7;
        int i = 0;
        for (; i < nw8; i += 8) {
            float v[8];
            #pragma unroll
            for (int u = 0; u < 8; u++) v[u] = p[(long)(i + u) * B];
            #pragma unroll
            for (int u = 0; u < 8; u++) s = fmaf(a, s, k * v[u]);
        }
        for (; i < nw; i++) s = fmaf(a, s, k * p[(long)i * B]);
    }

    // --- main: batch-8 load / compute-in-place / store ---
    {
        const float* pm = x + (long)t0 * B + c;
        float* po = out + (long)t0 * B + c;
        int n = tend - t0;
        int n8 = n & ~7;
        int j = 0;
        for (; j < n8; j += 8) {
            const float* pm8 = pm + (long)j * B;
            float v[8];
            #pragma unroll
            for (int u = 0; u < 8; u++) v[u] = __ldcs(pm8 + (long)u * B);
            #pragma unroll
            for (int u = 0; u < 8; u++) {
                float o = fmaf(b0, v[u], s);
                s = fmaf(a, s, k * v[u]);    // s = k*x + a*s
                v[u] = o;                    // reuse v[] as output buffer
            }
            float* po8 = po + (long)j * B;
            #pragma unroll
            for (int u = 0; u < 8; u++) {
                __stcs(po8, v[u]);
                po8 += B;
            }
        }
        for (; j < n; j++) {
            float xv = __ldcs(pm + (long)j * B);
            float o = fmaf(b0, xv, s);
            __stcs(&po[(long)j * B], o);
            s = fmaf(a, s, k * xv);
        }
    }

    if (finalDst && tend == T) finalDst[c] = s;
}

// ---------------------------------------------------------------------------

extern "C" void kernel_launch(void* const* d_in, const int* in_sizes, int n_in,
                              void* d_out, int out_size) {
    const float* x     = (const float*)d_in[0];
    const float* state = (const float*)d_in[1];
    const float* b0    = (const float*)d_in[2];
    const float* b1    = (const float*)d_in[3];
    const float* a1    = (const float*)d_in[4];
    float* out = (float*)d_out;

    long TB = in_sizes[0];
    int  B  = in_sizes[1];
    int  T  = (int)(TB / B);

    bool writeFinal = ((long)out_size >= TB + B);
    float* finalDst = writeFinal ? (out + TB) : nullptr;

    const int TPB = 256;
    int xBlocks = (B + TPB - 1) / TPB;                 // 16 for B=4096

    // choose numChunks so total blocks ~= 4 per SM (592 on 148 SMs)
    int numChunks = (NUM_SMS * 4) / xBlocks;           // 37
    if (numChunks < 1) numChunks = 1;
    if (numChunks > T) numChunks = T;
    int L = (T + numChunks - 1) / numChunks;           // 443
    numChunks = (T + L - 1) / L;                       // 37

    dim3 grid(xBlocks, numChunks);
    k_fused<<<grid, TPB>>>(x, state, b0, b1, a1, out, finalDst, T, B, L);
}